// round 5
// baseline (speedup 1.0000x reference)
#include <cuda_runtime.h>
#include <math.h>

#define BB    1024   // batch
#define DD    1024   // embed dim
#define NE    128    // num experts / N
#define PT    28     // PT_DEPTH
#define KSEL  32     // k-1 (softmax'd top count)
#define BPB   128    // batch rows per k_out block

// ---------------- scratch (device globals; no allocation allowed) ----------
__device__ float g_h[PT * DD];                     // silu(t*w1+b1) per step
__device__ __align__(16) float g_te[PT * DD];      // t_embed per unique step
__device__ float g_clean[PT * NE];                 // clean logits per step
__device__ float g_std[PT * NE];                   // noise std per step
__device__ float g_gates[BB * NE];                 // per-row gates
__device__ int   g_ts[BB];                         // decoded timesteps
__device__ int   g_step;                           // timestep[0]

// ---------------- 0) decode timestep buffer (int32 OR int64) ---------------
// If int64: first 1024 words = [t0,0,t1,0,...] -> all odd words 0.
// If int32: odd words are random in [0,28); all-zero is impossible.
__global__ void k_decode(const int* __restrict__ raw) {
    __shared__ int is32;
    int tid = threadIdx.x;
    if (tid == 0) is32 = 0;
    __syncthreads();
    int w = raw[tid];                 // words 0..1023: valid either way
    if ((tid & 1) && w != 0) atomicOr(&is32, 1);
    __syncthreads();
    int v = is32 ? raw[tid] : raw[2 * tid];
    g_ts[tid] = v;
    if (tid == 0) g_step = v;
}

// ---------------- 1) h[s,i] = silu(s * w1[i] + b1[i]) ----------------------
__global__ void k_h(const float* __restrict__ w1, const float* __restrict__ b1) {
    int s = blockIdx.x, i = threadIdx.x;
    float x = (float)s * w1[i] + b1[i];
    g_h[s * DD + i] = x / (1.0f + expf(-x));       // silu
}

// ---------------- 2) t_embed[s,j] = dot(h[s,:], w2[j,:]) + b2[j] -----------
__global__ __launch_bounds__(128) void k_embed(const float* __restrict__ w2,
                                               const float* __restrict__ b2) {
    int lane = threadIdx.x & 31;
    int j = blockIdx.x * 4 + (threadIdx.x >> 5);
    const float* w2row = w2 + (size_t)j * DD;
    float acc[PT];
#pragma unroll
    for (int s = 0; s < PT; s++) acc[s] = 0.0f;
    for (int i = lane; i < DD; i += 32) {
        float wv = w2row[i];
#pragma unroll
        for (int s = 0; s < PT; s++) acc[s] += g_h[s * DD + i] * wv;
    }
#pragma unroll
    for (int s = 0; s < PT; s++) {
#pragma unroll
        for (int o = 16; o > 0; o >>= 1)
            acc[s] += __shfl_xor_sync(0xffffffffu, acc[s], o);
    }
    if (lane == 0) {
        float bb = b2[j];
#pragma unroll
        for (int s = 0; s < PT; s++) g_te[s * DD + j] = acc[s] + bb;
    }
}

// ---------------- 3) clean[s,n], std[s,n] ----------------------------------
// One block per step s; thread-per-n. te row staged in smem (broadcast LDS).
// w_noise[j*NE+n] is coalesced across threads; gate_w[n,:] streams per thread.
__global__ __launch_bounds__(NE) void k_gate(const float* __restrict__ gate_w,
                                             const float* __restrict__ gate_b,
                                             const float* __restrict__ w_noise) {
    __shared__ float ste[DD];
    int s = blockIdx.x;
    int n = threadIdx.x;
#pragma unroll
    for (int j = n; j < DD; j += NE) ste[j] = g_te[s * DD + j];
    __syncthreads();
    const float* gw = gate_w + (size_t)n * (DD + 1);
    float ac = 0.0f, as = 0.0f;
#pragma unroll 4
    for (int j = 0; j < DD; j++) {
        float t = ste[j];
        ac += t * gw[j];
        as += t * w_noise[(size_t)j * NE + n];
    }
    g_clean[s * NE + n] = ac + (float)g_step * gw[DD] + gate_b[n];
    float sp = (as > 20.0f) ? as : log1pf(expf(as));   // softplus
    g_std[s * NE + n] = sp + 0.01f;                    // NOISE_EPS
}

// ---------------- 4) per-row noisy top-32 softmax gates --------------------
// Exact-rank selection matches jax.lax.top_k's stable tie-break.
__global__ __launch_bounds__(NE) void k_topk(const float* __restrict__ noise) {
    __shared__ float sv[NE];
    __shared__ float red[NE];
    __shared__ float smax;
    int b = blockIdx.x, n = threadIdx.x;
    int s = g_ts[b];
    float v = g_clean[s * NE + n] + noise[(size_t)b * NE + n] * g_std[s * NE + n];
    sv[n] = v;
    __syncthreads();
    int rank = 0;
#pragma unroll 8
    for (int m = 0; m < NE; m++) {
        float u = sv[m];
        rank += (u > v) || (u == v && m < n);
    }
    if (rank == 0) smax = v;   // unique by tie-break
    __syncthreads();
    float e = (rank < KSEL) ? expf(v - smax) : 0.0f;
    red[n] = e;
    __syncthreads();
#pragma unroll
    for (int o = NE / 2; o > 0; o >>= 1) {
        if (n < o) red[n] += red[n + o];
        __syncthreads();
    }
    g_gates[b * NE + n] = e / red[0];
}

// ---------------- 5) out[b,n,:] = gates[b,n] * prompts[step,n,:] -----------
// One block per (n, 128-batch-slab). Prompt row lives in registers; 128
// streaming stores per thread (deep MLP, evict-first so the 512MB write
// stream doesn't thrash L2). Prompt L2 read traffic: 512MB -> 4MB.
__global__ __launch_bounds__(256) void k_out(const float* __restrict__ prompt,
                                             float* __restrict__ out) {
    __shared__ float sg[BPB];
    int n = blockIdx.x;
    int b0 = blockIdx.y * BPB;
    int t = threadIdx.x;
    if (t < BPB) sg[t] = g_gates[(size_t)(b0 + t) * NE + n];
    float4 p = ((const float4*)(prompt + ((size_t)(g_step * NE + n)) * DD))[t];
    __syncthreads();
    float4* ob = (float4*)out + ((size_t)b0 * NE + n) * (DD / 4) + t;
#pragma unroll 16
    for (int b = 0; b < BPB; b++) {
        float g = sg[b];
        float4 o;
        o.x = g * p.x; o.y = g * p.y; o.z = g * p.z; o.w = g * p.w;
        __stcs(ob, o);
        ob += (size_t)NE * (DD / 4);
    }
}

// ---------------- 6) t_embed output: gather dedup'd rows -------------------
__global__ __launch_bounds__(256) void k_temb(float* __restrict__ out) {
    int b = blockIdx.x, t = threadIdx.x;
    int s = g_ts[b];
    float4 v = ((const float4*)(g_te + (size_t)s * DD))[t];
    __stcs((float4*)out + (size_t)b * (DD / 4) + t, v);
}

// ---------------- launch ---------------------------------------------------
extern "C" void kernel_launch(void* const* d_in, const int* in_sizes, int n_in,
                              void* d_out, int out_size) {
    const float* prompt  = (const float*)d_in[0];  // [28,128,1024]
    const float* w1      = (const float*)d_in[1];  // [1024,1]
    const float* b1      = (const float*)d_in[2];  // [1024]
    const float* w2      = (const float*)d_in[3];  // [1024,1024]
    const float* b2      = (const float*)d_in[4];  // [1024]
    const float* gate_w  = (const float*)d_in[5];  // [128,1025]
    const float* gate_b  = (const float*)d_in[6];  // [128]
    const float* w_noise = (const float*)d_in[7];  // [1024,128]
    const float* noise   = (const float*)d_in[8];  // [1024,128]
    const int*   tsraw   = (const int*)d_in[9];    // int32 or int64, detected
    float* out = (float*)d_out;

    k_decode<<<1, BB>>>(tsraw);
    k_h<<<PT, DD>>>(w1, b1);
    k_embed<<<DD / 4, 128>>>(w2, b2);
    k_gate<<<PT, NE>>>(gate_w, gate_b, w_noise);
    k_topk<<<BB, NE>>>(noise);
    dim3 go(NE, BB / BPB);
    k_out<<<go, 256>>>(prompt, out);

    size_t main_sz = (size_t)BB * NE * DD;
    if ((size_t)out_size >= main_sz + (size_t)BB * DD)
        k_temb<<<BB, 256>>>(out + main_sz);
}

// round 6
// speedup vs baseline: 1.0805x; 1.0805x over previous
#include <cuda_runtime.h>
#include <math.h>

#define BB    1024   // batch
#define DD    1024   // embed dim
#define NE    128    // num experts / N
#define PT    28     // PT_DEPTH
#define KSEL  32     // k-1 (softmax'd top count)
#define BPB   128    // batch rows per k_out block
#define JC    16     // j-chunks for std partials
#define JW    (DD / JC)  // 64 j per chunk

// ---------------- scratch (device globals; no allocation allowed) ----------
__device__ float g_h[PT * DD];                     // silu(t*w1+b1) per step
__device__ __align__(16) float g_te[PT * DD];      // t_embed per unique step
__device__ float g_clean[PT * NE];                 // clean logits per step
__device__ float g_std[PT * NE];                   // noise std per step
__device__ float g_sp[PT * JC * NE];               // std partial dots
__device__ float g_gates[BB * NE];                 // per-row gates
__device__ int   g_ts[BB];                         // decoded timesteps
__device__ int   g_step;                           // timestep[0]

// ---------------- 0) decode timestep buffer (int32 OR int64) ---------------
// If int64: first 1024 words = [t0,0,t1,0,...] -> all odd words 0.
// If int32: odd words are random in [0,28); all-zero is impossible.
__global__ void k_decode(const int* __restrict__ raw) {
    __shared__ int is32;
    int tid = threadIdx.x;
    if (tid == 0) is32 = 0;
    __syncthreads();
    int w = raw[tid];                 // words 0..1023: valid either way
    if ((tid & 1) && w != 0) atomicOr(&is32, 1);
    __syncthreads();
    int v = is32 ? raw[tid] : raw[2 * tid];
    g_ts[tid] = v;
    if (tid == 0) g_step = v;
}

// ---------------- 1) h[s,i] = silu(s * w1[i] + b1[i]) ----------------------
__global__ void k_h(const float* __restrict__ w1, const float* __restrict__ b1) {
    int s = blockIdx.x, i = threadIdx.x;
    float x = (float)s * w1[i] + b1[i];
    g_h[s * DD + i] = x / (1.0f + expf(-x));       // silu
}

// ---------------- 2) t_embed[s,j] = dot(h[s,:], w2[j,:]) + b2[j] -----------
__global__ __launch_bounds__(128) void k_embed(const float* __restrict__ w2,
                                               const float* __restrict__ b2) {
    int lane = threadIdx.x & 31;
    int j = blockIdx.x * 4 + (threadIdx.x >> 5);
    const float* w2row = w2 + (size_t)j * DD;
    float acc[PT];
#pragma unroll
    for (int s = 0; s < PT; s++) acc[s] = 0.0f;
    for (int i = lane; i < DD; i += 32) {
        float wv = w2row[i];
#pragma unroll
        for (int s = 0; s < PT; s++) acc[s] += g_h[s * DD + i] * wv;
    }
#pragma unroll
    for (int s = 0; s < PT; s++) {
#pragma unroll
        for (int o = 16; o > 0; o >>= 1)
            acc[s] += __shfl_xor_sync(0xffffffffu, acc[s], o);
    }
    if (lane == 0) {
        float bb = b2[j];
#pragma unroll
        for (int s = 0; s < PT; s++) g_te[s * DD + j] = acc[s] + bb;
    }
}

// ---------------- 3a) clean[s,n] = te[s,:].gate_w[n,:D] + step*gw[D] + b ---
// Warp per n (k_embed pattern): gate_w row coalesced across lanes; 28
// per-step accumulators; te reads hit L1/L2 (112KB total working set).
__global__ __launch_bounds__(128) void k_clean(const float* __restrict__ gate_w,
                                               const float* __restrict__ gate_b) {
    int lane = threadIdx.x & 31;
    int n = blockIdx.x * 4 + (threadIdx.x >> 5);
    const float* gw = gate_w + (size_t)n * (DD + 1);
    float acc[PT];
#pragma unroll
    for (int s = 0; s < PT; s++) acc[s] = 0.0f;
    for (int j = lane; j < DD; j += 32) {
        float wv = gw[j];
#pragma unroll
        for (int s = 0; s < PT; s++) acc[s] += g_te[s * DD + j] * wv;
    }
#pragma unroll
    for (int s = 0; s < PT; s++) {
#pragma unroll
        for (int o = 16; o > 0; o >>= 1)
            acc[s] += __shfl_xor_sync(0xffffffffu, acc[s], o);
    }
    if (lane == 0) {
        float tail = (float)g_step * gw[DD] + gate_b[n];
#pragma unroll
        for (int s = 0; s < PT; s++) g_clean[s * NE + n] = acc[s] + tail;
    }
}

// ---------------- 3b) std partials: g_sp[s,jc,n] ---------------------------
// Block per (s, j-chunk); thread = n -> w_noise[j*NE+n] coalesced.
// Deterministic two-stage reduction (no float atomics).
__global__ __launch_bounds__(NE) void k_stdp(const float* __restrict__ w_noise) {
    __shared__ float ste[JW];
    int s = blockIdx.x, jc = blockIdx.y;
    int n = threadIdx.x;
    if (n < JW) ste[n] = g_te[s * DD + jc * JW + n];
    __syncthreads();
    const float* wn = w_noise + (size_t)(jc * JW) * NE + n;
    float as = 0.0f;
#pragma unroll 8
    for (int j = 0; j < JW; j++) as += ste[j] * wn[(size_t)j * NE];
    g_sp[(s * JC + jc) * NE + n] = as;
}

// ---------------- 3c) std finalize: softplus(sum partials) + eps -----------
__global__ __launch_bounds__(NE) void k_stdf() {
    int s = blockIdx.x, n = threadIdx.x;
    float as = 0.0f;
#pragma unroll
    for (int jc = 0; jc < JC; jc++) as += g_sp[(s * JC + jc) * NE + n];
    float sp = (as > 20.0f) ? as : log1pf(expf(as));   // softplus
    g_std[s * NE + n] = sp + 0.01f;                    // NOISE_EPS
}

// ---------------- 4) per-row noisy top-32 softmax gates --------------------
// Exact-rank selection matches jax.lax.top_k's stable tie-break.
__global__ __launch_bounds__(NE) void k_topk(const float* __restrict__ noise) {
    __shared__ float sv[NE];
    __shared__ float red[NE];
    __shared__ float smax;
    int b = blockIdx.x, n = threadIdx.x;
    int s = g_ts[b];
    float v = g_clean[s * NE + n] + noise[(size_t)b * NE + n] * g_std[s * NE + n];
    sv[n] = v;
    __syncthreads();
    int rank = 0;
#pragma unroll 8
    for (int m = 0; m < NE; m++) {
        float u = sv[m];
        rank += (u > v) || (u == v && m < n);
    }
    if (rank == 0) smax = v;   // unique by tie-break
    __syncthreads();
    float e = (rank < KSEL) ? expf(v - smax) : 0.0f;
    red[n] = e;
    __syncthreads();
#pragma unroll
    for (int o = NE / 2; o > 0; o >>= 1) {
        if (n < o) red[n] += red[n + o];
        __syncthreads();
    }
    g_gates[b * NE + n] = e / red[0];
}

// ---------------- 5) out[b,n,:] = gates[b,n] * prompts[step,n,:] -----------
// One block per (n, 128-batch-slab). Prompt row lives in registers; 128
// streaming stores per thread (deep MLP, evict-first so the 512MB write
// stream doesn't thrash L2). Prompt L2 read traffic: 512MB -> 4MB.
__global__ __launch_bounds__(256) void k_out(const float* __restrict__ prompt,
                                             float* __restrict__ out) {
    __shared__ float sg[BPB];
    int n = blockIdx.x;
    int b0 = blockIdx.y * BPB;
    int t = threadIdx.x;
    if (t < BPB) sg[t] = g_gates[(size_t)(b0 + t) * NE + n];
    float4 p = ((const float4*)(prompt + ((size_t)(g_step * NE + n)) * DD))[t];
    __syncthreads();
    float4* ob = (float4*)out + ((size_t)b0 * NE + n) * (DD / 4) + t;
#pragma unroll 16
    for (int b = 0; b < BPB; b++) {
        float g = sg[b];
        float4 o;
        o.x = g * p.x; o.y = g * p.y; o.z = g * p.z; o.w = g * p.w;
        __stcs(ob, o);
        ob += (size_t)NE * (DD / 4);
    }
}

// ---------------- 6) t_embed output: gather dedup'd rows -------------------
__global__ __launch_bounds__(256) void k_temb(float* __restrict__ out) {
    int b = blockIdx.x, t = threadIdx.x;
    int s = g_ts[b];
    float4 v = ((const float4*)(g_te + (size_t)s * DD))[t];
    __stcs((float4*)out + (size_t)b * (DD / 4) + t, v);
}

// ---------------- launch ---------------------------------------------------
extern "C" void kernel_launch(void* const* d_in, const int* in_sizes, int n_in,
                              void* d_out, int out_size) {
    const float* prompt  = (const float*)d_in[0];  // [28,128,1024]
    const float* w1      = (const float*)d_in[1];  // [1024,1]
    const float* b1      = (const float*)d_in[2];  // [1024]
    const float* w2      = (const float*)d_in[3];  // [1024,1024]
    const float* b2      = (const float*)d_in[4];  // [1024]
    const float* gate_w  = (const float*)d_in[5];  // [128,1025]
    const float* gate_b  = (const float*)d_in[6];  // [128]
    const float* w_noise = (const float*)d_in[7];  // [1024,128]
    const float* noise   = (const float*)d_in[8];  // [1024,128]
    const int*   tsraw   = (const int*)d_in[9];    // int32 or int64, detected
    float* out = (float*)d_out;

    k_decode<<<1, BB>>>(tsraw);
    k_h<<<PT, DD>>>(w1, b1);
    k_embed<<<DD / 4, 128>>>(w2, b2);
    k_clean<<<NE / 4, 128>>>(gate_w, gate_b);
    dim3 gsp(PT, JC);
    k_stdp<<<gsp, NE>>>(w_noise);
    k_stdf<<<PT, NE>>>();
    k_topk<<<BB, NE>>>(noise);
    dim3 go(NE, BB / BPB);
    k_out<<<go, 256>>>(prompt, out);

    size_t main_sz = (size_t)BB * NE * DD;
    if ((size_t)out_size >= main_sz + (size_t)BB * DD)
        k_temb<<<BB, 256>>>(out + main_sz);
}

// round 8
// speedup vs baseline: 1.7873x; 1.6542x over previous
#include <cuda_runtime.h>
#include <math.h>

#define BB    1024   // batch
#define DD    1024   // embed dim
#define NE    128    // num experts / N
#define PT    28     // PT_DEPTH
#define KSEL  32     // k-1 (softmax'd top count)
#define BPB   128    // batch rows per k_out block
#define JC    16     // j-chunks for std partials
#define JW    (DD / JC)  // 64 j per chunk

// ---------------- scratch (device globals; no allocation allowed) ----------
__device__ float g_h[PT * DD];                     // silu(t*w1+b1) per step
__device__ __align__(16) float g_te[PT * DD];      // t_embed per unique step
__device__ float g_clean[PT * NE];                 // clean logits per step
__device__ float g_std[PT * NE];                   // noise std per step
__device__ float g_sp[PT * JC * NE];               // std partial dots
__device__ float g_gates[BB * NE];                 // per-row gates
__device__ int   g_ts[BB];                         // decoded timesteps
__device__ int   g_step;                           // timestep[0]

// ---------------- 0) decode timestep buffer (int32 OR int64) ---------------
// If int64: first 1024 words = [t0,0,t1,0,...] -> all odd words 0.
// If int32: odd words are random in [0,28); all-zero is impossible.
__global__ void k_decode(const int* __restrict__ raw) {
    __shared__ int is32;
    int tid = threadIdx.x;
    if (tid == 0) is32 = 0;
    __syncthreads();
    int w = raw[tid];                 // words 0..1023: valid either way
    if ((tid & 1) && w != 0) atomicOr(&is32, 1);
    __syncthreads();
    int v = is32 ? raw[tid] : raw[2 * tid];
    g_ts[tid] = v;
    if (tid == 0) g_step = v;
}

// ---------------- 1) h[s,i] = silu(s * w1[i] + b1[i]) ----------------------
__global__ void k_h(const float* __restrict__ w1, const float* __restrict__ b1) {
    int s = blockIdx.x, i = threadIdx.x;
    float x = (float)s * w1[i] + b1[i];
    g_h[s * DD + i] = x / (1.0f + expf(-x));       // silu
}

// ---------------- 2) t_embed[s,j] = dot(h[s,:], w2[j,:]) + b2[j] -----------
// Block per j (1024 blocks). w2 row staged in smem once (coalesced, read
// exactly once from DRAM). 4 warps x 7 steps each: only 7 accs/lane so
// ptxas keeps loads batched; g_h (112KB) hits L1/L2.
__global__ __launch_bounds__(128) void k_embed(const float* __restrict__ w2,
                                               const float* __restrict__ b2) {
    __shared__ float sw[DD];
    int j = blockIdx.x;
    int t = threadIdx.x;
    int lane = t & 31, w = t >> 5;
    const float* w2row = w2 + (size_t)j * DD;
#pragma unroll
    for (int i = t; i < DD; i += 128) sw[i] = w2row[i];
    __syncthreads();
    int s0 = w * 7;                   // warp w handles steps s0..s0+6
    float acc[7];
#pragma unroll
    for (int q = 0; q < 7; q++) acc[q] = 0.0f;
    for (int i = lane; i < DD; i += 32) {
        float wv = sw[i];
#pragma unroll
        for (int q = 0; q < 7; q++) acc[q] += g_h[(s0 + q) * DD + i] * wv;
    }
#pragma unroll
    for (int q = 0; q < 7; q++) {
#pragma unroll
        for (int o = 16; o > 0; o >>= 1)
            acc[q] += __shfl_xor_sync(0xffffffffu, acc[q], o);
    }
    if (lane == 0) {
        float bb = b2[j];
#pragma unroll
        for (int q = 0; q < 7; q++) g_te[(s0 + q) * DD + j] = acc[q] + bb;
    }
}

// ---------------- 3a) clean[s,n] = te[s,:].gate_w[n,:D] + step*gw[D] + b ---
// Block per (s,n) = 3584 blocks: latency hidden by sheer parallelism.
// Both reads j-contiguous -> coalesced; te + gate_w are L2-resident.
__global__ __launch_bounds__(128) void k_clean(const float* __restrict__ gate_w,
                                               const float* __restrict__ gate_b) {
    __shared__ float red[4];
    int s = blockIdx.x, n = blockIdx.y;
    int t = threadIdx.x;
    int lane = t & 31;
    const float* gw = gate_w + (size_t)n * (DD + 1);
    const float* te = g_te + (size_t)s * DD;
    float a = 0.0f;
#pragma unroll
    for (int j = t; j < DD; j += 128) a += te[j] * gw[j];
#pragma unroll
    for (int o = 16; o > 0; o >>= 1) a += __shfl_xor_sync(0xffffffffu, a, o);
    if (lane == 0) red[t >> 5] = a;
    __syncthreads();
    if (t == 0) {
        float sum = red[0] + red[1] + red[2] + red[3];
        g_clean[s * NE + n] = sum + (float)g_step * gw[DD] + gate_b[n];
    }
}

// ---------------- 3b) std partials: g_sp[s,jc,n] ---------------------------
// Block per (s, j-chunk); thread = n -> w_noise[j*NE+n] coalesced.
// Deterministic two-stage reduction (no float atomics).
__global__ __launch_bounds__(NE) void k_stdp(const float* __restrict__ w_noise) {
    __shared__ float ste[JW];
    int s = blockIdx.x, jc = blockIdx.y;
    int n = threadIdx.x;
    if (n < JW) ste[n] = g_te[s * DD + jc * JW + n];
    __syncthreads();
    const float* wn = w_noise + (size_t)(jc * JW) * NE + n;
    float as = 0.0f;
#pragma unroll 8
    for (int j = 0; j < JW; j++) as += ste[j] * wn[(size_t)j * NE];
    g_sp[(s * JC + jc) * NE + n] = as;
}

// ---------------- 3c) std finalize: softplus(sum partials) + eps -----------
__global__ __launch_bounds__(NE) void k_stdf() {
    int s = blockIdx.x, n = threadIdx.x;
    float as = 0.0f;
#pragma unroll
    for (int jc = 0; jc < JC; jc++) as += g_sp[(s * JC + jc) * NE + n];
    float sp = (as > 20.0f) ? as : log1pf(expf(as));   // softplus
    g_std[s * NE + n] = sp + 0.01f;                    // NOISE_EPS
}

// ---------------- 4) per-row noisy top-32 softmax gates --------------------
// Exact-rank selection matches jax.lax.top_k's stable tie-break.
__global__ __launch_bounds__(NE) void k_topk(const float* __restrict__ noise) {
    __shared__ float sv[NE];
    __shared__ float red[NE];
    __shared__ float smax;
    int b = blockIdx.x, n = threadIdx.x;
    int s = g_ts[b];
    float v = g_clean[s * NE + n] + noise[(size_t)b * NE + n] * g_std[s * NE + n];
    sv[n] = v;
    __syncthreads();
    int rank = 0;
#pragma unroll 8
    for (int m = 0; m < NE; m++) {
        float u = sv[m];
        rank += (u > v) || (u == v && m < n);
    }
    if (rank == 0) smax = v;   // unique by tie-break
    __syncthreads();
    float e = (rank < KSEL) ? expf(v - smax) : 0.0f;
    red[n] = e;
    __syncthreads();
#pragma unroll
    for (int o = NE / 2; o > 0; o >>= 1) {
        if (n < o) red[n] += red[n + o];
        __syncthreads();
    }
    g_gates[b * NE + n] = e / red[0];
}

// ---------------- 5) out[b,n,:] = gates[b,n] * prompts[step,n,:] -----------
// One block per (n, 128-batch-slab). Prompt row lives in registers; 128
// streaming stores per thread (deep MLP, evict-first so the 512MB write
// stream doesn't thrash L2). Prompt L2 read traffic: 512MB -> 4MB.
__global__ __launch_bounds__(256) void k_out(const float* __restrict__ prompt,
                                             float* __restrict__ out) {
    __shared__ float sg[BPB];
    int n = blockIdx.x;
    int b0 = blockIdx.y * BPB;
    int t = threadIdx.x;
    if (t < BPB) sg[t] = g_gates[(size_t)(b0 + t) * NE + n];
    float4 p = ((const float4*)(prompt + ((size_t)(g_step * NE + n)) * DD))[t];
    __syncthreads();
    float4* ob = (float4*)out + ((size_t)b0 * NE + n) * (DD / 4) + t;
#pragma unroll 16
    for (int b = 0; b < BPB; b++) {
        float g = sg[b];
        float4 o;
        o.x = g * p.x; o.y = g * p.y; o.z = g * p.z; o.w = g * p.w;
        __stcs(ob, o);
        ob += (size_t)NE * (DD / 4);
    }
}

// ---------------- 6) t_embed output: gather dedup'd rows -------------------
__global__ __launch_bounds__(256) void k_temb(float* __restrict__ out) {
    int b = blockIdx.x, t = threadIdx.x;
    int s = g_ts[b];
    float4 v = ((const float4*)(g_te + (size_t)s * DD))[t];
    __stcs((float4*)out + (size_t)b * (DD / 4) + t, v);
}

// ---------------- launch ---------------------------------------------------
extern "C" void kernel_launch(void* const* d_in, const int* in_sizes, int n_in,
                              void* d_out, int out_size) {
    const float* prompt  = (const float*)d_in[0];  // [28,128,1024]
    const float* w1      = (const float*)d_in[1];  // [1024,1]
    const float* b1      = (const float*)d_in[2];  // [1024]
    const float* w2      = (const float*)d_in[3];  // [1024,1024]
    const float* b2      = (const float*)d_in[4];  // [1024]
    const float* gate_w  = (const float*)d_in[5];  // [128,1025]
    const float* gate_b  = (const float*)d_in[6];  // [128]
    const float* w_noise = (const float*)d_in[7];  // [1024,128]
    const float* noise   = (const float*)d_in[8];  // [1024,128]
    const int*   tsraw   = (const int*)d_in[9];    // int32 or int64, detected
    float* out = (float*)d_out;

    k_decode<<<1, BB>>>(tsraw);
    k_h<<<PT, DD>>>(w1, b1);
    k_embed<<<DD, 128>>>(w2, b2);
    dim3 gc(PT, NE);
    k_clean<<<gc, 128>>>(gate_w, gate_b);
    dim3 gsp(PT, JC);
    k_stdp<<<gsp, NE>>>(w_noise);
    k_stdf<<<PT, NE>>>();
    k_topk<<<BB, NE>>>(noise);
    dim3 go(NE, BB / BPB);
    k_out<<<go, 256>>>(prompt, out);

    size_t main_sz = (size_t)BB * NE * DD;
    if ((size_t)out_size >= main_sz + (size_t)BB * DD)
        k_temb<<<BB, 256>>>(out + main_sz);
}